// round 5
// baseline (speedup 1.0000x reference)
#include <cuda_runtime.h>

// Abbott STDP step, fused single kernel (non-persistent). D=8, B=2, N=2048.
// Out = concat(W_prev[B,N,N], W_new[B,N,N], xbar_pre_new[D,B,N], xbar_post_new[B,N])

#define DD 8
#define BB 2
#define NN 2048
#define ALPHA_P 0.95f
#define ALPHA_D 0.90f

static const long long N2  = (long long)NN * NN;       // 4,194,304
static const long long BN2 = (long long)BB * N2;       // 8,388,608
static const long long DBN = (long long)DD * BB * NN;  // 32,768
static const long long BN  = (long long)BB * NN;       // 4,096

// One block per pre-neuron row e (grid=2048) — hardware block scheduler
// provides inter-row overlap (a new block's loads issue while old blocks
// drain epilogues); a persistent loop with per-row barriers measurably
// destroys that overlap (R3: -7% DRAM util). dmap (134 MB) read exactly
// once via both-batch accumulation. Trace updates fused in.
__global__ __launch_bounds__(512, 2) void stdp_fused(
    const float* __restrict__ Xd,        // (D,B,N)
    const float* __restrict__ Xpost,     // (B,N)
    const float* __restrict__ xbar_pre,  // (D,B,N)
    const float* __restrict__ xbar_post, // (B,N)
    const float* __restrict__ W,         // (B,N,N)
    const float* __restrict__ dmap,      // (D,N,N)
    const float* __restrict__ A_p,       // (N,N)
    const float* __restrict__ A_d,       // (N,N)
    float* __restrict__ W_prev_out,
    float* __restrict__ W_new_out,
    float* __restrict__ pre_out,         // (D,B,N) or nullptr
    float* __restrict__ post_out)        // (B,N)   or nullptr
{
    const int e = blockIdx.x;

    __shared__ float s_pre[DD * BB];
    __shared__ float s_xd[DD * BB];
    if (threadIdx.x < DD * BB) {
        const size_t idx = (size_t)threadIdx.x * NN + e;  // (d*BB+b)*NN + e
        const float xp = xbar_pre[idx];
        const float xv = Xd[idx];
        s_pre[threadIdx.x] = xp;
        s_xd[threadIdx.x]  = xv;
        if (pre_out)
            pre_out[idx] = fmaf(ALPHA_P, xp, (1.0f - ALPHA_P) * xv);
    }

    const int o = threadIdx.x << 2;                 // 0..2044 step 4
    const size_t row = (size_t)e * NN + o;

    // Independent of smem — issue before the barrier so they're in flight
    // while the block waits on the 16 trace loads.
    const float4 ap = *(const float4*)(A_p + row);
    const float4 ad = *(const float4*)(A_d + row);

    float4 dm[DD];
#pragma unroll
    for (int d = 0; d < DD; d++)
        dm[d] = *(const float4*)(dmap + (size_t)d * N2 + row);

    __syncthreads();

#pragma unroll
    for (int b = 0; b < BB; b++) {
        float4 sp = make_float4(0.f, 0.f, 0.f, 0.f);
        float4 sd = make_float4(0.f, 0.f, 0.f, 0.f);
#pragma unroll
        for (int d = 0; d < DD; d++) {
            const float xp = s_pre[d * BB + b];
            const float xv = s_xd[d * BB + b];
            sp.x = fmaf(xp, dm[d].x, sp.x);
            sp.y = fmaf(xp, dm[d].y, sp.y);
            sp.z = fmaf(xp, dm[d].z, sp.z);
            sp.w = fmaf(xp, dm[d].w, sp.w);
            sd.x = fmaf(xv, dm[d].x, sd.x);
            sd.y = fmaf(xv, dm[d].y, sd.y);
            sd.z = fmaf(xv, dm[d].z, sd.z);
            sd.w = fmaf(xv, dm[d].w, sd.w);
        }

        const size_t widx = (size_t)b * N2 + row;
        const float4 w   = *(const float4*)(W + widx);
        const float4 xpo = *(const float4*)(Xpost + (size_t)b * NN + o);
        const float4 xbp = *(const float4*)(xbar_post + (size_t)b * NN + o);

        float4 wn;
        wn.x = fminf(fmaxf(w.x + xpo.x * sp.x * ap.x - xbp.x * sd.x * ad.x, 0.f), 1.f);
        wn.y = fminf(fmaxf(w.y + xpo.y * sp.y * ap.y - xbp.y * sd.y * ad.y, 0.f), 1.f);
        wn.z = fminf(fmaxf(w.z + xpo.z * sp.z * ap.z - xbp.z * sd.z * ad.z, 0.f), 1.f);
        wn.w = fminf(fmaxf(w.w + xpo.w * sp.w * ap.w - xbp.w * sd.w * ad.w, 0.f), 1.f);

        *(float4*)(W_prev_out + widx) = w;
        *(float4*)(W_new_out  + widx) = wn;

        // Fused post-trace update: block 0 only (B*N = 4096 floats total).
        if (post_out && e == 0) {
            float4 pn;
            pn.x = fmaf(ALPHA_D, xbp.x, (1.0f - ALPHA_D) * xpo.x);
            pn.y = fmaf(ALPHA_D, xbp.y, (1.0f - ALPHA_D) * xpo.y);
            pn.z = fmaf(ALPHA_D, xbp.z, (1.0f - ALPHA_D) * xpo.z);
            pn.w = fmaf(ALPHA_D, xbp.w, (1.0f - ALPHA_D) * xpo.w);
            *(float4*)(post_out + (size_t)b * NN + o) = pn;
        }
    }
}

// Fallback: output is only W_prev (straight copy of W).
__global__ void copy_w(const float* __restrict__ W, float* __restrict__ out, long long n)
{
    const long long i = (long long)blockIdx.x * blockDim.x + threadIdx.x;
    if (i * 4 < n) {
        *(float4*)(out + i * 4) = *(const float4*)(W + i * 4);
    }
}

extern "C" void kernel_launch(void* const* d_in, const int* in_sizes, int n_in,
                              void* d_out, int out_size)
{
    const float* Xd        = (const float*)d_in[0];
    const float* Xpost     = (const float*)d_in[1];
    const float* xbar_pre  = (const float*)d_in[2];
    const float* xbar_post = (const float*)d_in[3];
    const float* W         = (const float*)d_in[4];
    const float* dmap      = (const float*)d_in[5];
    const float* A_p       = (const float*)d_in[6];
    const float* A_d       = (const float*)d_in[7];

    float* out = (float*)d_out;
    const long long total = 2 * BN2 + DBN + BN;  // 16,814,080

    if ((long long)out_size >= total) {
        float* W_prev   = out;
        float* W_new    = out + BN2;
        float* pre_o    = out + 2 * BN2;
        float* post_o   = pre_o + DBN;
        stdp_fused<<<NN, 512>>>(Xd, Xpost, xbar_pre, xbar_post, W, dmap,
                                A_p, A_d, W_prev, W_new, pre_o, post_o);
    } else if ((long long)out_size >= 2 * BN2) {
        stdp_fused<<<NN, 512>>>(Xd, Xpost, xbar_pre, xbar_post, W, dmap,
                                A_p, A_d, out, out + BN2,
                                (float*)nullptr, (float*)nullptr);
    } else {
        copy_w<<<(int)((BN2 / 4 + 255) / 256), 256>>>(W, out, BN2);
    }
}

// round 6
// speedup vs baseline: 1.1357x; 1.1357x over previous
#include <cuda_runtime.h>

// Abbott STDP step, fused single kernel. D=8, B=2, N=2048.
// Out = concat(W_prev[B,N,N], W_new[B,N,N], xbar_pre_new[D,B,N], xbar_post_new[B,N])
//
// Structure notes (measured, do not regress):
//  - R2 loop shape is load-bearing: load dmap INSIDE the d-loop, consume
//    immediately into 4 float4 accumulators (both batches in one sweep).
//    Front-loading dm[8] into registers cost +3.8us (R4).
//  - Persistent blocks with per-row barriers cost -7% DRAM util (R3).
//  - This version removes smem + __syncthreads entirely: warp-local scalar
//    load + __shfl broadcast, so warps are fully independent.

#define DD 8
#define BB 2
#define NN 2048
#define ALPHA_P 0.95f
#define ALPHA_D 0.90f

static const long long N2  = (long long)NN * NN;       // 4,194,304
static const long long BN2 = (long long)BB * N2;       // 8,388,608
static const long long DBN = (long long)DD * BB * NN;  // 32,768
static const long long BN  = (long long)BB * NN;       // 4,096

__global__ __launch_bounds__(512, 2) void stdp_fused(
    const float* __restrict__ Xd,        // (D,B,N)
    const float* __restrict__ Xpost,     // (B,N)
    const float* __restrict__ xbar_pre,  // (D,B,N)
    const float* __restrict__ xbar_post, // (B,N)
    const float* __restrict__ W,         // (B,N,N)
    const float* __restrict__ dmap,      // (D,N,N)
    const float* __restrict__ A_p,       // (N,N)
    const float* __restrict__ A_d,       // (N,N)
    float* __restrict__ W_prev_out,
    float* __restrict__ W_new_out,
    float* __restrict__ pre_out,         // (D,B,N) or nullptr
    float* __restrict__ post_out)        // (B,N)   or nullptr
{
    const int e    = blockIdx.x;
    const int lane = threadIdx.x & 31;

    // Warp-local broadcast of the 2*D*B=32 per-row scalars:
    // lane l<16 holds xbar_pre[(l)*NN+e]  (index l = d*BB+b)
    // lane l>=16 holds Xd[(l-16)*NN+e]
    const float* sbase = (lane < 16) ? xbar_pre : Xd;
    const float v = __ldg(sbase + (size_t)(lane & 15) * NN + e);

    // Fused pre-trace output: warp 0, lanes 0..15 (one value each).
    const float vpartner = __shfl_xor_sync(0xffffffffu, v, 16);
    if (pre_out && threadIdx.x < 16)
        pre_out[(size_t)threadIdx.x * NN + e] =
            fmaf(ALPHA_P, v, (1.0f - ALPHA_P) * vpartner);

    const int o = (threadIdx.x) << 2;               // 0..2044 step 4
    const size_t row = (size_t)e * NN + o;

    const float4 ap = *(const float4*)(A_p + row);
    const float4 ad = *(const float4*)(A_d + row);

    // Accumulate pot/dep sums for both batches in one sweep over d.
    float4 sp0 = make_float4(0.f, 0.f, 0.f, 0.f);
    float4 sd0 = sp0, sp1 = sp0, sd1 = sp0;
#pragma unroll
    for (int d = 0; d < DD; d++) {
        const float4 dm = *(const float4*)(dmap + (size_t)d * N2 + row);
        const float p0 = __shfl_sync(0xffffffffu, v, d * 2 + 0);
        const float p1 = __shfl_sync(0xffffffffu, v, d * 2 + 1);
        const float v0 = __shfl_sync(0xffffffffu, v, 16 + d * 2 + 0);
        const float v1 = __shfl_sync(0xffffffffu, v, 16 + d * 2 + 1);
        sp0.x = fmaf(p0, dm.x, sp0.x); sp0.y = fmaf(p0, dm.y, sp0.y);
        sp0.z = fmaf(p0, dm.z, sp0.z); sp0.w = fmaf(p0, dm.w, sp0.w);
        sd0.x = fmaf(v0, dm.x, sd0.x); sd0.y = fmaf(v0, dm.y, sd0.y);
        sd0.z = fmaf(v0, dm.z, sd0.z); sd0.w = fmaf(v0, dm.w, sd0.w);
        sp1.x = fmaf(p1, dm.x, sp1.x); sp1.y = fmaf(p1, dm.y, sp1.y);
        sp1.z = fmaf(p1, dm.z, sp1.z); sp1.w = fmaf(p1, dm.w, sp1.w);
        sd1.x = fmaf(v1, dm.x, sd1.x); sd1.y = fmaf(v1, dm.y, sd1.y);
        sd1.z = fmaf(v1, dm.z, sd1.z); sd1.w = fmaf(v1, dm.w, sd1.w);
    }

#pragma unroll
    for (int b = 0; b < BB; b++) {
        const float4 sp = b == 0 ? sp0 : sp1;
        const float4 sd = b == 0 ? sd0 : sd1;

        const size_t widx = (size_t)b * N2 + row;
        const float4 w   = *(const float4*)(W + widx);
        const float4 xpo = *(const float4*)(Xpost + (size_t)b * NN + o);
        const float4 xbp = *(const float4*)(xbar_post + (size_t)b * NN + o);

        float4 wn;
        wn.x = fminf(fmaxf(w.x + xpo.x * sp.x * ap.x - xbp.x * sd.x * ad.x, 0.f), 1.f);
        wn.y = fminf(fmaxf(w.y + xpo.y * sp.y * ap.y - xbp.y * sd.y * ad.y, 0.f), 1.f);
        wn.z = fminf(fmaxf(w.z + xpo.z * sp.z * ap.z - xbp.z * sd.z * ad.z, 0.f), 1.f);
        wn.w = fminf(fmaxf(w.w + xpo.w * sp.w * ap.w - xbp.w * sd.w * ad.w, 0.f), 1.f);

        *(float4*)(W_prev_out + widx) = w;
        *(float4*)(W_new_out  + widx) = wn;

        // Fused post-trace update: block 0 only (B*N = 4096 floats total).
        if (post_out && e == 0) {
            float4 pn;
            pn.x = fmaf(ALPHA_D, xbp.x, (1.0f - ALPHA_D) * xpo.x);
            pn.y = fmaf(ALPHA_D, xbp.y, (1.0f - ALPHA_D) * xpo.y);
            pn.z = fmaf(ALPHA_D, xbp.z, (1.0f - ALPHA_D) * xpo.z);
            pn.w = fmaf(ALPHA_D, xbp.w, (1.0f - ALPHA_D) * xpo.w);
            *(float4*)(post_out + (size_t)b * NN + o) = pn;
        }
    }
}

// Fallback: output is only W_prev (straight copy of W).
__global__ void copy_w(const float* __restrict__ W, float* __restrict__ out, long long n)
{
    const long long i = (long long)blockIdx.x * blockDim.x + threadIdx.x;
    if (i * 4 < n) {
        *(float4*)(out + i * 4) = *(const float4*)(W + i * 4);
    }
}

extern "C" void kernel_launch(void* const* d_in, const int* in_sizes, int n_in,
                              void* d_out, int out_size)
{
    const float* Xd        = (const float*)d_in[0];
    const float* Xpost     = (const float*)d_in[1];
    const float* xbar_pre  = (const float*)d_in[2];
    const float* xbar_post = (const float*)d_in[3];
    const float* W         = (const float*)d_in[4];
    const float* dmap      = (const float*)d_in[5];
    const float* A_p       = (const float*)d_in[6];
    const float* A_d       = (const float*)d_in[7];

    float* out = (float*)d_out;
    const long long total = 2 * BN2 + DBN + BN;  // 16,814,080

    if ((long long)out_size >= total) {
        float* W_prev   = out;
        float* W_new    = out + BN2;
        float* pre_o    = out + 2 * BN2;
        float* post_o   = pre_o + DBN;
        stdp_fused<<<NN, 512>>>(Xd, Xpost, xbar_pre, xbar_post, W, dmap,
                                A_p, A_d, W_prev, W_new, pre_o, post_o);
    } else if ((long long)out_size >= 2 * BN2) {
        stdp_fused<<<NN, 512>>>(Xd, Xpost, xbar_pre, xbar_post, W, dmap,
                                A_p, A_d, out, out + BN2,
                                (float*)nullptr, (float*)nullptr);
    } else {
        copy_w<<<(int)((BN2 / 4 + 255) / 256), 256>>>(W, out, BN2);
    }
}